// round 2
// baseline (speedup 1.0000x reference)
#include <cuda_runtime.h>
#include <cstdint>

// Problem constants
#define Bq    2
#define Nseq  2048
#define Cdim  1024
#define Hh    16
#define HDd   64
#define SCALE 0.125f           // 64^-0.5
#define Mrows (Bq*Nseq)        // 4096

// Scratch (device globals; no allocation allowed)
__device__ float g_q[(size_t)Bq*Hh*Nseq*HDd];   // [B,H,N,HD], pre-scaled by SCALE
__device__ float g_k[(size_t)Bq*Hh*Nseq*HDd];
__device__ float g_v[(size_t)Bq*Hh*Nseq*HDd];
__device__ float g_ao[(size_t)Mrows*Cdim];      // attention out, [B*N, C]

// ---------------------------------------------------------------------------
// Tiled fp32 SGEMM, NT form: out[m,j] = sum_k A[m,k] * W[j,k]
// BM=BN=128, BK=16, 256 threads, 8x8 per-thread tile.
// MODE 0: A = x, W = qkv_w -> scatter into g_q/g_k/g_v (head-major), scale Q.
// MODE 1: A = g_ao, W = proj_w -> out + bias.
// ---------------------------------------------------------------------------
template<int MODE>
__global__ void __launch_bounds__(256) gemm_nt_kernel(
    const float* __restrict__ A, const float* __restrict__ W,
    const float* __restrict__ bias, float* __restrict__ out)
{
    __shared__ float As[16][128];
    __shared__ float Bs[16][128];

    const int tid     = threadIdx.x;
    const int rowBase = blockIdx.y * 128;
    const int colBase = blockIdx.x * 128;
    const int lr = tid >> 2;           // loader row 0..63
    const int lc = (tid & 3) << 2;     // loader k-offset {0,4,8,12}
    const int ty = tid >> 4;           // 0..15
    const int tx = tid & 15;           // 0..15

    const float* Aptr = (MODE == 0) ? A : g_ao;

    const float* Ap0 = Aptr + (size_t)(rowBase + lr) * Cdim + lc;
    const float* Ap1 = Ap0 + (size_t)64 * Cdim;
    const float* Wp0 = W + (size_t)(colBase + lr) * Cdim + lc;
    const float* Wp1 = Wp0 + (size_t)64 * Cdim;

    float acc[8][8];
#pragma unroll
    for (int i = 0; i < 8; i++)
#pragma unroll
        for (int j = 0; j < 8; j++) acc[i][j] = 0.f;

    for (int k0 = 0; k0 < Cdim; k0 += 16) {
        float4 a0 = *(const float4*)(Ap0 + k0);
        float4 a1 = *(const float4*)(Ap1 + k0);
        float4 w0 = *(const float4*)(Wp0 + k0);
        float4 w1 = *(const float4*)(Wp1 + k0);
        __syncthreads();
        As[lc+0][lr]    = a0.x; As[lc+1][lr]    = a0.y; As[lc+2][lr]    = a0.z; As[lc+3][lr]    = a0.w;
        As[lc+0][lr+64] = a1.x; As[lc+1][lr+64] = a1.y; As[lc+2][lr+64] = a1.z; As[lc+3][lr+64] = a1.w;
        Bs[lc+0][lr]    = w0.x; Bs[lc+1][lr]    = w0.y; Bs[lc+2][lr]    = w0.z; Bs[lc+3][lr]    = w0.w;
        Bs[lc+0][lr+64] = w1.x; Bs[lc+1][lr+64] = w1.y; Bs[lc+2][lr+64] = w1.z; Bs[lc+3][lr+64] = w1.w;
        __syncthreads();
#pragma unroll
        for (int k = 0; k < 16; k++) {
            float4 a0v = ((const float4*)As[k])[ty*2];
            float4 a1v = ((const float4*)As[k])[ty*2+1];
            float4 b0v = ((const float4*)Bs[k])[tx*2];
            float4 b1v = ((const float4*)Bs[k])[tx*2+1];
            float av[8] = {a0v.x,a0v.y,a0v.z,a0v.w,a1v.x,a1v.y,a1v.z,a1v.w};
            float bv[8] = {b0v.x,b0v.y,b0v.z,b0v.w,b1v.x,b1v.y,b1v.z,b1v.w};
#pragma unroll
            for (int i = 0; i < 8; i++)
#pragma unroll
                for (int j = 0; j < 8; j++)
                    acc[i][j] += av[i] * bv[j];
        }
    }

    if (MODE == 0) {
#pragma unroll
        for (int i = 0; i < 8; i++) {
            int m  = rowBase + ty*8 + i;
            int bb = m >> 11;            // /Nseq
            int n  = m & (Nseq-1);
#pragma unroll
            for (int j = 0; j < 8; j++) {
                int col   = colBase + tx*8 + j;
                int which = col >> 10;       // 0=q 1=k 2=v
                int c     = col & (Cdim-1);
                int hh    = c >> 6;
                int d     = c & 63;
                size_t idx = (((size_t)bb*Hh + hh)*Nseq + n)*HDd + d;
                float v = acc[i][j];
                if (which == 0)       g_q[idx] = v * SCALE;
                else if (which == 1)  g_k[idx] = v;
                else                  g_v[idx] = v;
            }
        }
    } else {
#pragma unroll
        for (int i = 0; i < 8; i++) {
            int m = rowBase + ty*8 + i;
            float* orow = out + (size_t)m * Cdim + colBase + tx*8;
#pragma unroll
            for (int j = 0; j < 8; j++)
                orow[j] = acc[i][j] + bias[colBase + tx*8 + j];
        }
    }
}

// ---------------------------------------------------------------------------
// Flash-style attention. Grid: (N/64, B*H). Block: 256 threads.
// Per block: 64 queries. Loop over 64-key chunks: S = Q K^T (+alibi +mask),
// online softmax, O += P V. Row stats held by 4-lane groups (shuffles).
// smem: Qs, Ks, Vs, Ps tiles of 64 x (stride 68) floats each = 69632 B dynamic.
// ---------------------------------------------------------------------------
#define ATTN_SMEM (4 * 64 * 68 * 4)

__global__ void __launch_bounds__(256) attn_kernel(
    const float* __restrict__ alibi, const int* __restrict__ pmask)
{
    extern __shared__ float sm[];
    float* Qs = sm;
    float* Ks = sm + 64*68;
    float* Vs = sm + 2*64*68;
    float* Ps = sm + 3*64*68;   // holds alibi tile, then P in-place
    __shared__ float maskadd[64];

    const int tid = threadIdx.x;
    const int bh  = blockIdx.y;       // b*H + h
    const int b   = bh >> 4;
    const int h   = bh & 15;
    const int q0  = blockIdx.x * 64;

    const int tg = tid & 3;           // 0..3 lane group within a query row
    const int qr = tid >> 2;          // 0..63 query row
    const int lrow = tid >> 2;        // loader row
    const int lf4  = tid & 3;         // loader float4 group

    // Load Q tile (pre-scaled)
    {
        const float* qb = g_q + ((size_t)bh * Nseq + q0) * HDd;
#pragma unroll
        for (int i = 0; i < 4; i++) {
            *(float4*)(Qs + lrow*68 + lf4*4 + i*16) =
                *(const float4*)(qb + (size_t)lrow*HDd + lf4*4 + i*16);
        }
    }

    float4 o[4];
#pragma unroll
    for (int jj = 0; jj < 4; jj++) o[jj] = make_float4(0.f,0.f,0.f,0.f);
    float m_run = -1e30f, l_run = 0.f;

    const float* kb_all = g_k + (size_t)bh * Nseq * HDd;
    const float* vb_all = g_v + (size_t)bh * Nseq * HDd;
    const float* abase  = alibi + ((size_t)bh * Nseq + q0) * Nseq;

    __syncthreads();   // Q tile visible

    for (int k0 = 0; k0 < Nseq; k0 += 64) {
        // stage K, V, alibi, mask for this chunk
        const float* kb = kb_all + (size_t)k0 * HDd;
        const float* vb = vb_all + (size_t)k0 * HDd;
#pragma unroll
        for (int i = 0; i < 4; i++) {
            *(float4*)(Ks + lrow*68 + lf4*4 + i*16) =
                *(const float4*)(kb + (size_t)lrow*HDd + lf4*4 + i*16);
            *(float4*)(Vs + lrow*68 + lf4*4 + i*16) =
                *(const float4*)(vb + (size_t)lrow*HDd + lf4*4 + i*16);
            *(float4*)(Ps + lrow*68 + lf4*4 + i*16) =
                *(const float4*)(abase + (size_t)lrow*Nseq + k0 + lf4*4 + i*16);
        }
        if (tid < 64)
            maskadd[tid] = (pmask[(size_t)b*Nseq + k0 + tid] != 0) ? -1e30f : 0.f;
        __syncthreads();

        // S = Q K^T : thread owns row qr, key cols kc = 4j+tg (j=0..15)
        float acc[16];
#pragma unroll
        for (int j = 0; j < 16; j++) acc[j] = 0.f;
#pragma unroll
        for (int d0 = 0; d0 < 64; d0 += 4) {
            float4 qv = *(const float4*)(Qs + qr*68 + d0);
#pragma unroll
            for (int j = 0; j < 16; j++) {
                float4 kv = *(const float4*)(Ks + (j*4 + tg)*68 + d0);
                acc[j] += qv.x*kv.x + qv.y*kv.y + qv.z*kv.z + qv.w*kv.w;
            }
        }

        // logits = S + alibi + mask ; online softmax
        float mx = -1e30f;
#pragma unroll
        for (int j = 0; j < 16; j++) {
            int kc = j*4 + tg;
            acc[j] += Ps[qr*68 + kc] + maskadd[kc];
            mx = fmaxf(mx, acc[j]);
        }
        mx = fmaxf(mx, __shfl_xor_sync(0xffffffffu, mx, 1));
        mx = fmaxf(mx, __shfl_xor_sync(0xffffffffu, mx, 2));
        float m_new = fmaxf(m_run, mx);
        float corr  = __expf(m_run - m_new);
        float ls = 0.f;
#pragma unroll
        for (int j = 0; j < 16; j++) {
            float p = __expf(acc[j] - m_new);
            ls += p;
            Ps[qr*68 + j*4 + tg] = p;   // overwrite alibi with P
        }
        ls += __shfl_xor_sync(0xffffffffu, ls, 1);
        ls += __shfl_xor_sync(0xffffffffu, ls, 2);
        l_run = l_run * corr + ls;
        m_run = m_new;
        __syncwarp();   // P writes by the 4 lanes of each row visible in-warp

        // O = O*corr + P V : thread owns row qr, dims d = 16*jj + 4*tg + 0..3
#pragma unroll
        for (int jj = 0; jj < 4; jj++) {
            o[jj].x *= corr; o[jj].y *= corr; o[jj].z *= corr; o[jj].w *= corr;
        }
        for (int kc = 0; kc < 64; kc++) {
            float p = Ps[qr*68 + kc];
#pragma unroll
            for (int jj = 0; jj < 4; jj++) {
                float4 v = *(const float4*)(Vs + kc*68 + jj*16 + tg*4);
                o[jj].x += p*v.x; o[jj].y += p*v.y; o[jj].z += p*v.z; o[jj].w += p*v.w;
            }
        }
        __syncthreads();   // done with Ks/Vs/Ps before next chunk overwrites
    }

    // finalize and store merged-head layout [B,N,H*HD]
    float inv = (l_run > 0.f) ? (1.f / l_run) : 0.f;
    float* dst = g_ao + ((size_t)b*Nseq + q0 + qr)*Cdim + h*HDd;
#pragma unroll
    for (int jj = 0; jj < 4; jj++) {
        o[jj].x *= inv; o[jj].y *= inv; o[jj].z *= inv; o[jj].w *= inv;
        *(float4*)(dst + jj*16 + tg*4) = o[jj];
    }
}

// ---------------------------------------------------------------------------
extern "C" void kernel_launch(void* const* d_in, const int* in_sizes, int n_in,
                              void* d_out, int out_size)
{
    const float* x      = (const float*)d_in[0];
    const int*   pmask  = (const int*)d_in[1];    // bool materialized as int32
    const float* alibi  = (const float*)d_in[2];
    const float* qkv_w  = (const float*)d_in[3];
    const float* proj_w = (const float*)d_in[4];
    const float* proj_b = (const float*)d_in[5];
    float*       out    = (float*)d_out;

    cudaFuncSetAttribute(attn_kernel,
                         cudaFuncAttributeMaxDynamicSharedMemorySize, ATTN_SMEM);

    // 1) QKV projection: [4096,1024] x [3072,1024]^T -> q/k/v head-major
    gemm_nt_kernel<0><<<dim3(24, 32), 256>>>(x, qkv_w, nullptr, nullptr);

    // 2) Attention: grid (q-tiles, B*H)
    attn_kernel<<<dim3(Nseq/64, Bq*Hh), 256, ATTN_SMEM>>>(alibi, pmask);

    // 3) Output projection: [4096,1024] x [1024,1024]^T + bias -> out
    gemm_nt_kernel<1><<<dim3(8, 32), 256>>>(nullptr, proj_w, proj_b, out);
}

// round 3
// speedup vs baseline: 3.2051x; 3.2051x over previous
#include <cuda_runtime.h>
#include <cuda_bf16.h>
#include <cstdint>

#define Bq    2
#define Nseq  2048
#define Cdim  1024
#define Hh    16
#define HDd   64
#define SCALE 0.125f
#define Mrows (Bq*Nseq)

// Scratch (device globals)
__device__ float         g_q  [(size_t)Bq*Hh*Nseq*HDd];   // fp32, pre-scaled
__device__ __nv_bfloat16 g_kh [(size_t)Bq*Hh*Nseq*HDd];   // K hi  [bh][key][dim]
__device__ __nv_bfloat16 g_kl [(size_t)Bq*Hh*Nseq*HDd];   // K lo
__device__ __nv_bfloat16 g_vth[(size_t)Bq*Hh*HDd*Nseq];   // V^T hi [bh][dim][key]
__device__ __nv_bfloat16 g_vtl[(size_t)Bq*Hh*HDd*Nseq];   // V^T lo
__device__ float         g_ao [(size_t)Mrows*Cdim];       // attention out

// ---------------------------------------------------------------------------
__device__ __forceinline__ void mma_bf16(float* d, const uint32_t* a, const uint32_t* b)
{
    asm volatile(
        "mma.sync.aligned.m16n8k16.row.col.f32.bf16.bf16.f32 "
        "{%0,%1,%2,%3}, {%4,%5,%6,%7}, {%8,%9}, {%0,%1,%2,%3};"
        : "+f"(d[0]), "+f"(d[1]), "+f"(d[2]), "+f"(d[3])
        : "r"(a[0]), "r"(a[1]), "r"(a[2]), "r"(a[3]), "r"(b[0]), "r"(b[1]));
}

// split two floats into packed bf16 hi pair + lo (residual) pair
__device__ __forceinline__ void split_pack(float x, float y, uint32_t& h, uint32_t& l)
{
    __nv_bfloat162 hv = __floats2bfloat162_rn(x, y);
    float hx = __bfloat162float(hv.x);
    float hy = __bfloat162float(hv.y);
    __nv_bfloat162 lv = __floats2bfloat162_rn(x - hx, y - hy);
    h = *reinterpret_cast<uint32_t*>(&hv);
    l = *reinterpret_cast<uint32_t*>(&lv);
}

// ---------------------------------------------------------------------------
// Split-bf16 tensor-core GEMM, NT: out[m,j] = sum_k A[m,k]*W[j,k]
// BM=BN=128, BK=32, 256 threads (8 warps as 2x4), warp tile 64x32.
// MODE 0: A=x, W=qkv_w -> scatter q (fp32*SCALE), k (bf16 h/l), v^T (bf16 h/l)
// MODE 1: A=g_ao, W=proj_w -> out + bias
// ---------------------------------------------------------------------------
#define PADK 20   // u32 stride: 16 pairs + pad (conflict-free frag loads)

template<int MODE>
__global__ void __launch_bounds__(256) gemm_mma(
    const float* __restrict__ A, const float* __restrict__ W,
    const float* __restrict__ bias, float* __restrict__ out)
{
    __shared__ uint32_t Ah[128*PADK], Al[128*PADK];
    __shared__ uint32_t Wh[128*PADK], Wl[128*PADK];

    const int tid  = threadIdx.x;
    const int lane = tid & 31;
    const int warp = tid >> 5;
    const int wm   = warp >> 2;          // 0..1
    const int wn   = warp & 3;           // 0..3
    const int rowBase = blockIdx.y * 128;
    const int colBase = blockIdx.x * 128;

    const int lr  = tid >> 1;            // staging row 0..127
    const int lcp = (tid & 1) * 8;       // staging pair offset (0 or 8)
    const int lcol = (tid & 1) * 16;     // staging float offset

    const float* Aptr = (MODE == 0) ? A : g_ao;
    const float* ap = Aptr + (size_t)(rowBase + lr) * Cdim + lcol;
    const float* wp = W    + (size_t)(colBase + lr) * Cdim + lcol;

    float acc[4][4][4];
#pragma unroll
    for (int mt = 0; mt < 4; mt++)
#pragma unroll
        for (int nt = 0; nt < 4; nt++)
#pragma unroll
            for (int i = 0; i < 4; i++) acc[mt][nt][i] = 0.f;

    for (int k0 = 0; k0 < Cdim; k0 += 32) {
        float4 av[4], wv[4];
#pragma unroll
        for (int i = 0; i < 4; i++) {
            av[i] = *(const float4*)(ap + k0 + i*4);
            wv[i] = *(const float4*)(wp + k0 + i*4);
        }
        __syncthreads();
#pragma unroll
        for (int i = 0; i < 4; i++) {
            uint32_t h, l;
            split_pack(av[i].x, av[i].y, h, l);
            Ah[lr*PADK + lcp + 2*i]   = h;  Al[lr*PADK + lcp + 2*i]   = l;
            split_pack(av[i].z, av[i].w, h, l);
            Ah[lr*PADK + lcp + 2*i+1] = h;  Al[lr*PADK + lcp + 2*i+1] = l;
            split_pack(wv[i].x, wv[i].y, h, l);
            Wh[lr*PADK + lcp + 2*i]   = h;  Wl[lr*PADK + lcp + 2*i]   = l;
            split_pack(wv[i].z, wv[i].w, h, l);
            Wh[lr*PADK + lcp + 2*i+1] = h;  Wl[lr*PADK + lcp + 2*i+1] = l;
        }
        __syncthreads();

#pragma unroll
        for (int ks = 0; ks < 2; ks++) {
            uint32_t fah[4][4], fal[4][4];
            const int p = ks*8 + (lane & 3);
#pragma unroll
            for (int mt = 0; mt < 4; mt++) {
                const int r = wm*64 + mt*16 + (lane >> 2);
                fah[mt][0] = Ah[r*PADK + p];       fal[mt][0] = Al[r*PADK + p];
                fah[mt][1] = Ah[(r+8)*PADK + p];   fal[mt][1] = Al[(r+8)*PADK + p];
                fah[mt][2] = Ah[r*PADK + p + 4];   fal[mt][2] = Al[r*PADK + p + 4];
                fah[mt][3] = Ah[(r+8)*PADK + p+4]; fal[mt][3] = Al[(r+8)*PADK + p+4];
            }
#pragma unroll
            for (int nt = 0; nt < 4; nt++) {
                const int n = wn*32 + nt*8 + (lane >> 2);
                uint32_t bh2[2] = { Wh[n*PADK + p], Wh[n*PADK + p + 4] };
                uint32_t bl2[2] = { Wl[n*PADK + p], Wl[n*PADK + p + 4] };
#pragma unroll
                for (int mt = 0; mt < 4; mt++) {
                    mma_bf16(acc[mt][nt], fah[mt], bh2);
                    mma_bf16(acc[mt][nt], fah[mt], bl2);
                    mma_bf16(acc[mt][nt], fal[mt], bh2);
                }
            }
        }
    }

    // epilogue
#pragma unroll
    for (int mt = 0; mt < 4; mt++) {
#pragma unroll
        for (int nt = 0; nt < 4; nt++) {
            const int r0 = rowBase + wm*64 + mt*16 + (lane >> 2);
            const int cc = colBase + wn*32 + nt*8 + 2*(lane & 3);
            if (MODE == 1) {
                float b0 = bias[cc], b1 = bias[cc+1];
                *(float2*)(out + (size_t)r0*Cdim + cc) =
                    make_float2(acc[mt][nt][0] + b0, acc[mt][nt][1] + b1);
                *(float2*)(out + (size_t)(r0+8)*Cdim + cc) =
                    make_float2(acc[mt][nt][2] + b0, acc[mt][nt][3] + b1);
            } else {
#pragma unroll
                for (int half = 0; half < 2; half++) {
                    const int m  = r0 + half*8;
                    const float v0 = acc[mt][nt][half*2 + 0];
                    const float v1 = acc[mt][nt][half*2 + 1];
                    const int bb = m >> 11, n = m & (Nseq-1);
                    const int which = cc >> 10, c = cc & (Cdim-1);
                    const int hh = c >> 6, d = c & 63;
                    const size_t bh = (size_t)bb*Hh + hh;
                    if (which == 0) {
                        const size_t idx = (bh*Nseq + n)*HDd + d;
                        *(float2*)(g_q + idx) = make_float2(v0*SCALE, v1*SCALE);
                    } else if (which == 1) {
                        const size_t idx = (bh*Nseq + n)*HDd + d;
                        uint32_t h, l;
                        split_pack(v0, v1, h, l);
                        *(uint32_t*)(g_kh + idx) = h;
                        *(uint32_t*)(g_kl + idx) = l;
                    } else {
                        const size_t idx = (bh*HDd + d)*Nseq + n;  // transposed
                        __nv_bfloat162 hv = __floats2bfloat162_rn(v0, v1);
                        float l0 = v0 - __bfloat162float(hv.x);
                        float l1 = v1 - __bfloat162float(hv.y);
                        __nv_bfloat162 lv = __floats2bfloat162_rn(l0, l1);
                        g_vth[idx]        = hv.x;  g_vtl[idx]        = lv.x;
                        g_vth[idx + Nseq] = hv.y;  g_vtl[idx + Nseq] = lv.y;
                    }
                }
            }
        }
    }
}

// ---------------------------------------------------------------------------
// Flash attention, split-bf16 mma. Grid: (N/64, B*H). Block: 128 (4 warps).
// Warp w owns query rows [w*16, w*16+16). Chunks of 64 keys.
// ---------------------------------------------------------------------------
#define PADA 36   // u32 stride: 32 pairs + pad

__global__ void __launch_bounds__(128) attn_mma(
    const float* __restrict__ alibi, const int* __restrict__ pmask)
{
    __shared__ uint32_t Kh[64*PADA], Kl[64*PADA];
    __shared__ uint32_t Vh[64*PADA], Vl[64*PADA];
    __shared__ float maskadd[64];

    const int tid  = threadIdx.x;
    const int lane = tid & 31;
    const int warp = tid >> 5;
    const int bh   = blockIdx.y;
    const int b    = bh >> 4;
    const int h    = bh & 15;
    const int q0   = blockIdx.x * 64;

    const int r0 = warp*16 + (lane >> 2);   // local query row (this thread: r0, r0+8)
    const int c2 = 2*(lane & 3);

    // Q fragments (register-resident for all chunks)
    uint32_t qh[4][4], ql[4][4];
    {
        const float* qbase = g_q + ((size_t)bh*Nseq + q0)*HDd;
#pragma unroll
        for (int ks = 0; ks < 4; ks++) {
            const float* p0 = qbase + (size_t)r0*HDd + ks*16 + c2;
            const float* p1 = p0 + 8*HDd;
            float2 e0 = *(const float2*)p0;
            float2 e1 = *(const float2*)p1;
            float2 e2 = *(const float2*)(p0 + 8);
            float2 e3 = *(const float2*)(p1 + 8);
            split_pack(e0.x, e0.y, qh[ks][0], ql[ks][0]);
            split_pack(e1.x, e1.y, qh[ks][1], ql[ks][1]);
            split_pack(e2.x, e2.y, qh[ks][2], ql[ks][2]);
            split_pack(e3.x, e3.y, qh[ks][3], ql[ks][3]);
        }
    }

    float o[8][4];
#pragma unroll
    for (int dt = 0; dt < 8; dt++)
#pragma unroll
        for (int i = 0; i < 4; i++) o[dt][i] = 0.f;
    float m0 = -1e30f, m1 = -1e30f, l0 = 0.f, l1 = 0.f;

    const uint32_t* kh_g = (const uint32_t*)(g_kh  + (size_t)bh*Nseq*HDd);
    const uint32_t* kl_g = (const uint32_t*)(g_kl  + (size_t)bh*Nseq*HDd);
    const uint32_t* vh_g = (const uint32_t*)(g_vth + (size_t)bh*HDd*Nseq);
    const uint32_t* vl_g = (const uint32_t*)(g_vtl + (size_t)bh*HDd*Nseq);
    const float*    ab   = alibi + ((size_t)bh*Nseq + q0)*Nseq;

    const int lr = tid >> 1;            // staging row (0..63)
    const int lc = (tid & 1) * 16;      // staging u32 offset (0 or 16)

    for (int k0 = 0; k0 < Nseq; k0 += 64) {
        __syncthreads();   // previous chunk's compute done
        {
            const uint32_t* sk_h = kh_g + (size_t)(k0 + lr)*32 + lc;
            const uint32_t* sk_l = kl_g + (size_t)(k0 + lr)*32 + lc;
            const uint32_t* sv_h = vh_g + (size_t)lr*(Nseq/2) + k0/2 + lc;
            const uint32_t* sv_l = vl_g + (size_t)lr*(Nseq/2) + k0/2 + lc;
#pragma unroll
            for (int i = 0; i < 4; i++) {
                *(uint4*)(Kh + lr*PADA + lc + i*4) = *(const uint4*)(sk_h + i*4);
                *(uint4*)(Kl + lr*PADA + lc + i*4) = *(const uint4*)(sk_l + i*4);
                *(uint4*)(Vh + lr*PADA + lc + i*4) = *(const uint4*)(sv_h + i*4);
                *(uint4*)(Vl + lr*PADA + lc + i*4) = *(const uint4*)(sv_l + i*4);
            }
            if (tid < 64)
                maskadd[tid] = (pmask[(size_t)b*Nseq + k0 + tid] != 0) ? -1e30f : 0.f;
        }
        __syncthreads();

        // S = Q K^T
        float s[8][4];
#pragma unroll
        for (int nt = 0; nt < 8; nt++)
#pragma unroll
            for (int i = 0; i < 4; i++) s[nt][i] = 0.f;
#pragma unroll
        for (int ks = 0; ks < 4; ks++) {
            const int p = ks*8 + (lane & 3);
#pragma unroll
            for (int nt = 0; nt < 8; nt++) {
                const int key = nt*8 + (lane >> 2);
                uint32_t bh2[2] = { Kh[key*PADA + p], Kh[key*PADA + p + 4] };
                uint32_t bl2[2] = { Kl[key*PADA + p], Kl[key*PADA + p + 4] };
                mma_bf16(s[nt], qh[ks], bh2);
                mma_bf16(s[nt], qh[ks], bl2);
                mma_bf16(s[nt], ql[ks], bh2);
            }
        }

        // + alibi + mask
#pragma unroll
        for (int nt = 0; nt < 8; nt++) {
            const int kc = nt*8 + c2;
            const float* arow = ab + (size_t)r0*Nseq + k0 + kc;
            float2 a0 = *(const float2*)arow;
            float2 a1 = *(const float2*)(arow + 8*Nseq);
            const float mk0 = maskadd[kc], mk1 = maskadd[kc+1];
            s[nt][0] += a0.x + mk0;  s[nt][1] += a0.y + mk1;
            s[nt][2] += a1.x + mk0;  s[nt][3] += a1.y + mk1;
        }

        // online softmax (rows r0 and r0+8)
        float mx0 = -1e30f, mx1 = -1e30f;
#pragma unroll
        for (int nt = 0; nt < 8; nt++) {
            mx0 = fmaxf(mx0, fmaxf(s[nt][0], s[nt][1]));
            mx1 = fmaxf(mx1, fmaxf(s[nt][2], s[nt][3]));
        }
        mx0 = fmaxf(mx0, __shfl_xor_sync(0xffffffffu, mx0, 1));
        mx0 = fmaxf(mx0, __shfl_xor_sync(0xffffffffu, mx0, 2));
        mx1 = fmaxf(mx1, __shfl_xor_sync(0xffffffffu, mx1, 1));
        mx1 = fmaxf(mx1, __shfl_xor_sync(0xffffffffu, mx1, 2));

        const float mn0 = fmaxf(m0, mx0), mn1 = fmaxf(m1, mx1);
        const float cr0 = __expf(m0 - mn0), cr1 = __expf(m1 - mn1);
        float ls0 = 0.f, ls1 = 0.f;
#pragma unroll
        for (int nt = 0; nt < 8; nt++) {
            s[nt][0] = __expf(s[nt][0] - mn0);
            s[nt][1] = __expf(s[nt][1] - mn0);
            s[nt][2] = __expf(s[nt][2] - mn1);
            s[nt][3] = __expf(s[nt][3] - mn1);
            ls0 += s[nt][0] + s[nt][1];
            ls1 += s[nt][2] + s[nt][3];
        }
        ls0 += __shfl_xor_sync(0xffffffffu, ls0, 1);
        ls0 += __shfl_xor_sync(0xffffffffu, ls0, 2);
        ls1 += __shfl_xor_sync(0xffffffffu, ls1, 1);
        ls1 += __shfl_xor_sync(0xffffffffu, ls1, 2);
        l0 = l0*cr0 + ls0;  l1 = l1*cr1 + ls1;
        m0 = mn0;           m1 = mn1;

#pragma unroll
        for (int dt = 0; dt < 8; dt++) {
            o[dt][0] *= cr0; o[dt][1] *= cr0;
            o[dt][2] *= cr1; o[dt][3] *= cr1;
        }

        // O += P V  (P fragments from softmaxed accumulators)
#pragma unroll
        for (int pk = 0; pk < 4; pk++) {
            uint32_t pa_h[4], pa_l[4];
            split_pack(s[2*pk][0],   s[2*pk][1],   pa_h[0], pa_l[0]);
            split_pack(s[2*pk][2],   s[2*pk][3],   pa_h[1], pa_l[1]);
            split_pack(s[2*pk+1][0], s[2*pk+1][1], pa_h[2], pa_l[2]);
            split_pack(s[2*pk+1][2], s[2*pk+1][3], pa_h[3], pa_l[3]);
            const int p = pk*8 + (lane & 3);
#pragma unroll
            for (int dt = 0; dt < 8; dt++) {
                const int dim = dt*8 + (lane >> 2);
                uint32_t vb_h[2] = { Vh[dim*PADA + p], Vh[dim*PADA + p + 4] };
                uint32_t vb_l[2] = { Vl[dim*PADA + p], Vl[dim*PADA + p + 4] };
                mma_bf16(o[dt], pa_h, vb_h);
                mma_bf16(o[dt], pa_h, vb_l);
                mma_bf16(o[dt], pa_l, vb_h);
            }
        }
    }

    // finalize: [B,N,H*HD]
    const float inv0 = (l0 > 0.f) ? (1.f/l0) : 0.f;
    const float inv1 = (l1 > 0.f) ? (1.f/l1) : 0.f;
    float* d0 = g_ao + ((size_t)b*Nseq + q0 + r0)*Cdim + h*HDd;
    float* d1 = d0 + 8*Cdim;
#pragma unroll
    for (int dt = 0; dt < 8; dt++) {
        *(float2*)(d0 + dt*8 + c2) = make_float2(o[dt][0]*inv0, o[dt][1]*inv0);
        *(float2*)(d1 + dt*8 + c2) = make_float2(o[dt][2]*inv1, o[dt][3]*inv1);
    }
}

// ---------------------------------------------------------------------------
extern "C" void kernel_launch(void* const* d_in, const int* in_sizes, int n_in,
                              void* d_out, int out_size)
{
    const float* x      = (const float*)d_in[0];
    const int*   pmask  = (const int*)d_in[1];
    const float* alibi  = (const float*)d_in[2];
    const float* qkv_w  = (const float*)d_in[3];
    const float* proj_w = (const float*)d_in[4];
    const float* proj_b = (const float*)d_in[5];
    float*       out    = (float*)d_out;

    gemm_mma<0><<<dim3(24, 32), 256>>>(x, qkv_w, nullptr, nullptr);
    attn_mma<<<dim3(Nseq/64, Bq*Hh), 128>>>(alibi, pmask);
    gemm_mma<1><<<dim3(8, 32), 256>>>(nullptr, proj_w, proj_b, out);
}